// round 2
// baseline (speedup 1.0000x reference)
#include <cuda_runtime.h>

#define N_ATOMS   65536
#define N_BONDS   131072
#define ATOM_FDIM 133
#define BOND_TOTAL 147
#define BOND_FDIM 14
#define HIDDEN    256
#define MAX_NB    6
#define N_MOLS    2048
#define NEI_LD    272   // 256 (nei_a) + 14 (nei_b) padded to 272

// ---------------- scratch (device globals; no allocation allowed) ----------
__device__ float g_inp[(size_t)N_ATOMS * HIDDEN];   // pre-relu input GEMM result
__device__ float g_msg[(size_t)N_ATOMS * HIDDEN];   // current message (post-relu)
__device__ float g_nei[(size_t)N_ATOMS * NEI_LD];   // [nei_a | nei_b | zero-pad]
__device__ float g_hid[(size_t)N_ATOMS * HIDDEN];   // atom hiddens (partial/final)
__device__ float g_WhP[(size_t)NEI_LD * HIDDEN];    // Wh zero-padded to 272 rows
__device__ int   g_start[N_MOLS];
__device__ int   g_count[N_MOLS];

// ---------------- small prep kernels ---------------------------------------
__global__ void pad_Wh_kernel(const float* __restrict__ Wh) {
    int idx = blockIdx.x * blockDim.x + threadIdx.x;   // 272*256 threads
    if (idx >= NEI_LD * HIDDEN) return;
    int k = idx / HIDDEN;
    g_WhP[idx] = (k < HIDDEN + BOND_FDIM) ? Wh[idx] : 0.0f;
}

__global__ void zero_count_kernel() {
    int i = blockIdx.x * blockDim.x + threadIdx.x;
    if (i < N_MOLS) g_count[i] = 0;
}

// ---------------- gathers --------------------------------------------------
// nei_a: g_nei[i, 0:256] = sum_j g_msg[a2a[i,j], :]
__global__ void gather_a_kernel(const int* __restrict__ a2a) {
    int atom = blockIdx.x * 4 + (threadIdx.x >> 6);   // 4 atoms per 256-thr block
    int c4   = threadIdx.x & 63;                      // float4 column 0..63
    int idx0 = a2a[atom * MAX_NB + 0];
    int idx1 = a2a[atom * MAX_NB + 1];
    int idx2 = a2a[atom * MAX_NB + 2];
    int idx3 = a2a[atom * MAX_NB + 3];
    int idx4 = a2a[atom * MAX_NB + 4];
    int idx5 = a2a[atom * MAX_NB + 5];
    float4 s = make_float4(0.f, 0.f, 0.f, 0.f);
    const float* m = g_msg;
    int col = c4 * 4;
    float4 v;
    v = *(const float4*)&m[(size_t)idx0 * HIDDEN + col]; s.x += v.x; s.y += v.y; s.z += v.z; s.w += v.w;
    v = *(const float4*)&m[(size_t)idx1 * HIDDEN + col]; s.x += v.x; s.y += v.y; s.z += v.z; s.w += v.w;
    v = *(const float4*)&m[(size_t)idx2 * HIDDEN + col]; s.x += v.x; s.y += v.y; s.z += v.z; s.w += v.w;
    v = *(const float4*)&m[(size_t)idx3 * HIDDEN + col]; s.x += v.x; s.y += v.y; s.z += v.z; s.w += v.w;
    v = *(const float4*)&m[(size_t)idx4 * HIDDEN + col]; s.x += v.x; s.y += v.y; s.z += v.z; s.w += v.w;
    v = *(const float4*)&m[(size_t)idx5 * HIDDEN + col]; s.x += v.x; s.y += v.y; s.z += v.z; s.w += v.w;
    *(float4*)&g_nei[(size_t)atom * NEI_LD + col] = s;
}

// nei_b: g_nei[i, 256+c] = sum_j f_bonds[a2b[i,j], 133+c] for c<14, 0 for c in 14..15
__global__ void gather_b_kernel(const int* __restrict__ a2b,
                                const float* __restrict__ f_bonds) {
    int atom = blockIdx.x * 16 + (threadIdx.x >> 4);  // 16 atoms per block
    int c    = threadIdx.x & 15;                      // 0..15
    float s = 0.f;
    if (c < BOND_FDIM) {
        #pragma unroll
        for (int j = 0; j < MAX_NB; j++) {
            int b = a2b[atom * MAX_NB + j];
            s += f_bonds[(size_t)b * BOND_TOTAL + (BOND_TOTAL - BOND_FDIM) + c];
        }
    }
    g_nei[(size_t)atom * NEI_LD + HIDDEN + c] = s;
}

// ---------------- SGEMM: C[M,256] = A[M,K] @ B[K,256] (+bias)(+res)(relu) ---
// MODE 0: v=acc+bias; C0=v; C1=relu(v)           (input GEMM)
// MODE 1: v=acc+bias+res; C1=relu(v)             (message update)
// MODE 2: C0=acc                                 (output GEMM pass 1)
// MODE 3: v=acc+bias+res; C0=relu(v)             (output GEMM pass 2)
#define BM 128
#define BN 128
#define BK 16

template <int MODE>
__global__ void __launch_bounds__(256)
sgemm_kernel(const float* __restrict__ A, int lda,
             const float* __restrict__ B,      // K x 256 row-major
             const float* __restrict__ bias,
             const float* __restrict__ res,
             float* __restrict__ C0, float* __restrict__ C1,
             int M, int K)
{
    __shared__ float As[BK][BM];
    __shared__ float Bs[BK][BN];

    int tid = threadIdx.x;
    int tx = tid & 15;          // output column group
    int ty = tid >> 4;          // output row group
    int row0 = blockIdx.y * BM;
    int col0 = blockIdx.x * BN;

    // A loader: thread (am, ak) loads A[row0+am][k0+ak .. +7]
    int am = tid & 127;
    int ak = (tid >> 7) * 8;
    const float* Arow = A + (size_t)(row0 + am) * lda;

    float acc[8][8];
    #pragma unroll
    for (int i = 0; i < 8; i++)
        #pragma unroll
        for (int j = 0; j < 8; j++) acc[i][j] = 0.f;

    for (int k0 = 0; k0 < K; k0 += BK) {
        // A tile (scalar loads: lda arbitrary)
        #pragma unroll
        for (int i = 0; i < 8; i++) {
            int kk = ak + i;
            As[kk][am] = (k0 + kk < K) ? Arow[k0 + kk] : 0.f;
        }
        // B tile (vector loads: width 256, 16B aligned)
        #pragma unroll
        for (int i = 0; i < 2; i++) {
            int f  = tid + i * 256;
            int kk = f >> 5;
            int n4 = (f & 31) * 4;
            float4 v = make_float4(0.f, 0.f, 0.f, 0.f);
            if (k0 + kk < K)
                v = *(const float4*)&B[(size_t)(k0 + kk) * HIDDEN + col0 + n4];
            *(float4*)&Bs[kk][n4] = v;
        }
        __syncthreads();

        #pragma unroll
        for (int k = 0; k < BK; k++) {
            float a[8], b[8];
            #pragma unroll
            for (int i = 0; i < 8; i++) a[i] = As[k][ty * 8 + i];
            #pragma unroll
            for (int j = 0; j < 8; j++) b[j] = Bs[k][tx * 8 + j];
            #pragma unroll
            for (int i = 0; i < 8; i++)
                #pragma unroll
                for (int j = 0; j < 8; j++)
                    acc[i][j] += a[i] * b[j];
        }
        __syncthreads();
    }

    // epilogue
    float4 b4[2];
    if (MODE == 0 || MODE == 1 || MODE == 3) {
        b4[0] = *(const float4*)&bias[col0 + tx * 8];
        b4[1] = *(const float4*)&bias[col0 + tx * 8 + 4];
    }
    #pragma unroll
    for (int i = 0; i < 8; i++) {
        size_t r = row0 + ty * 8 + i;
        size_t base = r * HIDDEN + col0 + tx * 8;
        #pragma unroll
        for (int jg = 0; jg < 2; jg++) {
            float4 v;
            v.x = acc[i][jg * 4 + 0];
            v.y = acc[i][jg * 4 + 1];
            v.z = acc[i][jg * 4 + 2];
            v.w = acc[i][jg * 4 + 3];
            if (MODE == 0 || MODE == 1 || MODE == 3) {
                v.x += b4[jg].x; v.y += b4[jg].y; v.z += b4[jg].z; v.w += b4[jg].w;
            }
            if (MODE == 1 || MODE == 3) {
                float4 rr = *(const float4*)&res[base + jg * 4];
                v.x += rr.x; v.y += rr.y; v.z += rr.z; v.w += rr.w;
            }
            if (MODE == 0) {
                *(float4*)&C0[base + jg * 4] = v;
                float4 m;
                m.x = fmaxf(v.x, 0.f); m.y = fmaxf(v.y, 0.f);
                m.z = fmaxf(v.z, 0.f); m.w = fmaxf(v.w, 0.f);
                *(float4*)&C1[base + jg * 4] = m;
            } else if (MODE == 1) {
                float4 m;
                m.x = fmaxf(v.x, 0.f); m.y = fmaxf(v.y, 0.f);
                m.z = fmaxf(v.z, 0.f); m.w = fmaxf(v.w, 0.f);
                *(float4*)&C1[base + jg * 4] = m;
            } else if (MODE == 2) {
                *(float4*)&C0[base + jg * 4] = v;
            } else {
                float4 m;
                m.x = fmaxf(v.x, 0.f); m.y = fmaxf(v.y, 0.f);
                m.z = fmaxf(v.z, 0.f); m.w = fmaxf(v.w, 0.f);
                *(float4*)&C0[base + jg * 4] = m;
            }
        }
    }
}

// ---------------- segment mean ---------------------------------------------
__global__ void seg_prep_kernel(const int* __restrict__ seg) {
    int i = blockIdx.x * blockDim.x + threadIdx.x;   // < N_ATOMS
    int s = seg[i];
    atomicAdd(&g_count[s], 1);
    if (i == 0 || seg[i - 1] != s) g_start[s] = i;
}

__global__ void seg_mean_kernel(float* __restrict__ out) {
    int m = blockIdx.x;          // molecule
    int c = threadIdx.x;         // column
    int cnt = g_count[m];
    float v = 0.f;
    if (cnt > 0) {
        int st = g_start[m];
        float s = 0.f;
        for (int r = 0; r < cnt; r++)
            s += g_hid[(size_t)(st + r) * HIDDEN + c];
        v = s / (float)cnt;
    }
    out[(size_t)m * HIDDEN + c] = v;
}

// ---------------- launch ----------------------------------------------------
extern "C" void kernel_launch(void* const* d_in, const int* in_sizes, int n_in,
                              void* d_out, int out_size) {
    const float* atom_features = (const float*)d_in[0];
    const float* f_bonds       = (const float*)d_in[1];
    const int*   a2a           = (const int*)d_in[2];
    const int*   a2b           = (const int*)d_in[3];
    const int*   seg           = (const int*)d_in[4];
    const float* Wi            = (const float*)d_in[5];
    const float* bi            = (const float*)d_in[6];
    const float* Wh            = (const float*)d_in[7];
    const float* bh            = (const float*)d_in[8];
    const float* Wo            = (const float*)d_in[9];
    const float* bo            = (const float*)d_in[10];
    float* out = (float*)d_out;

    float *inp, *msg, *nei, *hid, *whp;
    cudaGetSymbolAddress((void**)&inp, g_inp);
    cudaGetSymbolAddress((void**)&msg, g_msg);
    cudaGetSymbolAddress((void**)&nei, g_nei);
    cudaGetSymbolAddress((void**)&hid, g_hid);
    cudaGetSymbolAddress((void**)&whp, g_WhP);

    dim3 gemm_grid(HIDDEN / BN, N_ATOMS / BM);   // (2, 512)

    // 0) pad Wh -> 272 rows
    pad_Wh_kernel<<<(NEI_LD * HIDDEN + 255) / 256, 256>>>(Wh);

    // 1) inp = atom_features @ Wi + bi ; msg = relu(inp)
    sgemm_kernel<0><<<gemm_grid, 256>>>(atom_features, ATOM_FDIM, Wi, bi,
                                        nullptr, inp, msg, N_ATOMS, ATOM_FDIM);

    // 2) bond-feature gather (loop-invariant): g_nei cols 256..271
    gather_b_kernel<<<N_ATOMS / 16, 256>>>(a2b, f_bonds);

    // 3) depth-1 = 2 message-passing iterations
    for (int it = 0; it < 2; it++) {
        gather_a_kernel<<<N_ATOMS / 4, 256>>>(a2a);
        sgemm_kernel<1><<<gemm_grid, 256>>>(nei, NEI_LD, whp, bh,
                                            inp, nullptr, msg, N_ATOMS, NEI_LD);
    }

    // 4) a_message gather (into g_nei cols 0..255)
    gather_a_kernel<<<N_ATOMS / 4, 256>>>(a2a);

    // 5) hidden = relu(atom_features @ Wo[:133] + a_message @ Wo[133:] + bo)
    sgemm_kernel<2><<<gemm_grid, 256>>>(atom_features, ATOM_FDIM, Wo, nullptr,
                                        nullptr, hid, nullptr, N_ATOMS, ATOM_FDIM);
    sgemm_kernel<3><<<gemm_grid, 256>>>(nei, NEI_LD, Wo + ATOM_FDIM * HIDDEN, bo,
                                        hid, hid, nullptr, N_ATOMS, HIDDEN);

    // 6) segment mean (sorted segment ids)
    zero_count_kernel<<<(N_MOLS + 255) / 256, 256>>>();
    seg_prep_kernel<<<N_ATOMS / 256, 256>>>(seg);
    seg_mean_kernel<<<N_MOLS, 256>>>(out);
}

// round 4
// speedup vs baseline: 2.0549x; 2.0549x over previous
#include <cuda_runtime.h>
#include <cuda_bf16.h>
#include <cstdint>

#define N_ATOMS   65536
#define ATOM_FDIM 133
#define BOND_TOTAL 147
#define BOND_FDIM 14
#define HIDDEN    256
#define MAX_NB    6
#define N_MOLS    2048

// padded K strides (multiples of 32)
#define LDA_AF   192   // 133 -> 192
#define LDA_NEI  320   // 272 -> 320

// ---------------- scratch (device globals) ----------------------------------
__device__ float g_inp[(size_t)N_ATOMS * HIDDEN];
__device__ float g_msg[(size_t)N_ATOMS * HIDDEN];
__device__ float g_hid[(size_t)N_ATOMS * HIDDEN];
__device__ __nv_bfloat16 g_AfH[(size_t)N_ATOMS * LDA_AF];
__device__ __nv_bfloat16 g_AfL[(size_t)N_ATOMS * LDA_AF];
__device__ __nv_bfloat16 g_neiH[(size_t)N_ATOMS * LDA_NEI];
__device__ __nv_bfloat16 g_neiL[(size_t)N_ATOMS * LDA_NEI];
// transposed, split weights: [256 rows(n) x lda cols(k)]
__device__ __nv_bfloat16 g_WiTH[(size_t)HIDDEN * LDA_AF];
__device__ __nv_bfloat16 g_WiTL[(size_t)HIDDEN * LDA_AF];
__device__ __nv_bfloat16 g_WhTH[(size_t)HIDDEN * LDA_NEI];
__device__ __nv_bfloat16 g_WhTL[(size_t)HIDDEN * LDA_NEI];
__device__ __nv_bfloat16 g_Wo1TH[(size_t)HIDDEN * LDA_AF];
__device__ __nv_bfloat16 g_Wo1TL[(size_t)HIDDEN * LDA_AF];
__device__ __nv_bfloat16 g_Wo2TH[(size_t)HIDDEN * HIDDEN];
__device__ __nv_bfloat16 g_Wo2TL[(size_t)HIDDEN * HIDDEN];
__device__ int g_start[N_MOLS];
__device__ int g_count[N_MOLS];

__device__ __forceinline__ void split_bf16(float v, __nv_bfloat16& h, __nv_bfloat16& l) {
    h = __float2bfloat16(v);
    l = __float2bfloat16(v - __bfloat162float(h));
}

__device__ __forceinline__ uint32_t smem_u32(const void* p) {
    uint32_t a;
    asm("{ .reg .u64 t; cvta.to.shared.u64 t, %1; cvt.u32.u64 %0, t; }" : "=r"(a) : "l"(p));
    return a;
}
__device__ __forceinline__ void cp_async16(uint32_t s, const void* g) {
    asm volatile("cp.async.cg.shared.global [%0], [%1], 16;" :: "r"(s), "l"(g));
}
__device__ __forceinline__ void cp_commit() {
    asm volatile("cp.async.commit_group;" ::: "memory");
}
template <int N>
__device__ __forceinline__ void cp_wait() {
    asm volatile("cp.async.wait_group %0;" :: "n"(N) : "memory");
}
__device__ __forceinline__ void ldm_x4(uint32_t& r0, uint32_t& r1, uint32_t& r2,
                                       uint32_t& r3, uint32_t addr) {
    asm volatile("ldmatrix.sync.aligned.m8n8.x4.shared.b16 {%0,%1,%2,%3}, [%4];"
                 : "=r"(r0), "=r"(r1), "=r"(r2), "=r"(r3) : "r"(addr));
}
__device__ __forceinline__ void ldm_x2(uint32_t& r0, uint32_t& r1, uint32_t addr) {
    asm volatile("ldmatrix.sync.aligned.m8n8.x2.shared.b16 {%0,%1}, [%2];"
                 : "=r"(r0), "=r"(r1) : "r"(addr));
}
__device__ __forceinline__ void mma16816(float* c, const uint32_t* a, const uint32_t* b) {
    asm volatile(
        "mma.sync.aligned.m16n8k16.row.col.f32.bf16.bf16.f32 "
        "{%0,%1,%2,%3}, {%4,%5,%6,%7}, {%8,%9}, {%0,%1,%2,%3};"
        : "+f"(c[0]), "+f"(c[1]), "+f"(c[2]), "+f"(c[3])
        : "r"(a[0]), "r"(a[1]), "r"(a[2]), "r"(a[3]), "r"(b[0]), "r"(b[1]));
}

// ---------------- prep kernels ----------------------------------------------
__global__ void conv_atoms_kernel(const float* __restrict__ af) {
    int idx = blockIdx.x * blockDim.x + threadIdx.x;
    if (idx >= N_ATOMS * LDA_AF) return;
    int r = idx / LDA_AF, c = idx - r * LDA_AF;
    float v = (c < ATOM_FDIM) ? af[(size_t)r * ATOM_FDIM + c] : 0.0f;
    __nv_bfloat16 h, l; split_bf16(v, h, l);
    g_AfH[idx] = h; g_AfL[idx] = l;
}

// transpose+split a weight block: src [Ksrc x 256] -> dst [256 x lda] (zero pad)
__global__ void conv_weight_kernel(const float* __restrict__ W, int Ksrc, int lda,
                                   __nv_bfloat16* __restrict__ dH,
                                   __nv_bfloat16* __restrict__ dL) {
    int idx = blockIdx.x * blockDim.x + threadIdx.x;
    if (idx >= HIDDEN * lda) return;
    int n = idx / lda, k = idx - n * lda;
    float v = (k < Ksrc) ? W[(size_t)k * HIDDEN + n] : 0.0f;
    __nv_bfloat16 h, l; split_bf16(v, h, l);
    dH[idx] = h; dL[idx] = l;
}

// ---------------- gathers ----------------------------------------------------
__global__ void gather_a_kernel(const int* __restrict__ a2a) {
    int atom = blockIdx.x * 4 + (threadIdx.x >> 6);
    int c4   = threadIdx.x & 63;
    int col  = c4 * 4;
    int i0 = a2a[atom * MAX_NB + 0], i1 = a2a[atom * MAX_NB + 1];
    int i2 = a2a[atom * MAX_NB + 2], i3 = a2a[atom * MAX_NB + 3];
    int i4 = a2a[atom * MAX_NB + 4], i5 = a2a[atom * MAX_NB + 5];
    const float* m = g_msg;
    float4 s = make_float4(0.f, 0.f, 0.f, 0.f);
    float4 v;
    v = *(const float4*)&m[(size_t)i0 * HIDDEN + col]; s.x+=v.x; s.y+=v.y; s.z+=v.z; s.w+=v.w;
    v = *(const float4*)&m[(size_t)i1 * HIDDEN + col]; s.x+=v.x; s.y+=v.y; s.z+=v.z; s.w+=v.w;
    v = *(const float4*)&m[(size_t)i2 * HIDDEN + col]; s.x+=v.x; s.y+=v.y; s.z+=v.z; s.w+=v.w;
    v = *(const float4*)&m[(size_t)i3 * HIDDEN + col]; s.x+=v.x; s.y+=v.y; s.z+=v.z; s.w+=v.w;
    v = *(const float4*)&m[(size_t)i4 * HIDDEN + col]; s.x+=v.x; s.y+=v.y; s.z+=v.z; s.w+=v.w;
    v = *(const float4*)&m[(size_t)i5 * HIDDEN + col]; s.x+=v.x; s.y+=v.y; s.z+=v.z; s.w+=v.w;
    __nv_bfloat16 h0,h1,h2,h3,l0,l1,l2,l3;
    split_bf16(s.x, h0, l0); split_bf16(s.y, h1, l1);
    split_bf16(s.z, h2, l2); split_bf16(s.w, h3, l3);
    uint2 ph, pl;
    ph.x = ((uint32_t)__bfloat16_as_ushort(h1) << 16) | __bfloat16_as_ushort(h0);
    ph.y = ((uint32_t)__bfloat16_as_ushort(h3) << 16) | __bfloat16_as_ushort(h2);
    pl.x = ((uint32_t)__bfloat16_as_ushort(l1) << 16) | __bfloat16_as_ushort(l0);
    pl.y = ((uint32_t)__bfloat16_as_ushort(l3) << 16) | __bfloat16_as_ushort(l2);
    *(uint2*)&g_neiH[(size_t)atom * LDA_NEI + col] = ph;
    *(uint2*)&g_neiL[(size_t)atom * LDA_NEI + col] = pl;
}

__global__ void gather_b_kernel(const int* __restrict__ a2b,
                                const float* __restrict__ f_bonds) {
    int atom = blockIdx.x * 4 + (threadIdx.x >> 6);
    int c    = threadIdx.x & 63;
    float s = 0.f;
    if (c < BOND_FDIM) {
        #pragma unroll
        for (int j = 0; j < MAX_NB; j++) {
            int b = a2b[atom * MAX_NB + j];
            s += f_bonds[(size_t)b * BOND_TOTAL + (BOND_TOTAL - BOND_FDIM) + c];
        }
    }
    __nv_bfloat16 h, l; split_bf16(s, h, l);
    g_neiH[(size_t)atom * LDA_NEI + HIDDEN + c] = h;
    g_neiL[(size_t)atom * LDA_NEI + HIDDEN + c] = l;
}

// ---------------- bf16x3 tensor-core GEMM (mma.sync) -------------------------
// C[M,256] = A[M,K] @ B[K,256]; Bt stored [256(n)][K]. 3-term compensated.
// MODE 0: v=acc+bias;      out0=v, out1=relu(v)
// MODE 1: v=acc+bias+res;  out1=relu(v)
// MODE 2: out0=acc
// MODE 3: v=acc+bias+res;  out0=relu(v)

#define BK       32
#define ROW_ELEM 40          // BK + 8 pad (bf16)
#define ROW_B    80          // bytes
#define TILE_B   (128 * ROW_B)   // 10240
#define OFF_AH   0
#define OFF_AL   TILE_B
#define OFF_BH   (2 * TILE_B)
#define OFF_BL   (3 * TILE_B)
#define STG_B    (4 * TILE_B)    // 40960
#define SMEM_TOTAL (2 * STG_B)   // 81920

template <int MODE>
__global__ void __launch_bounds__(256, 2)
tc_gemm(const __nv_bfloat16* __restrict__ Ahg, const __nv_bfloat16* __restrict__ Alg, int ldaA,
        const __nv_bfloat16* __restrict__ Bhg, const __nv_bfloat16* __restrict__ Blg, int ldaB,
        int chunks,
        const float* __restrict__ bias, const float* __restrict__ res,
        float* __restrict__ out0, float* __restrict__ out1)
{
    extern __shared__ char smem[];
    uint32_t sb = smem_u32(smem);
    const int tid  = threadIdx.x;
    const int wid  = tid >> 5;
    const int lane = tid & 31;
    const int row0 = blockIdx.y * 128;       // M block
    const int n0   = blockIdx.x * 128;       // N block
    const int warp_m = (wid >> 2) * 64;      // 0 or 64
    const int warp_n = (wid & 3) * 32;       // 0,32,64,96

    float acc[4][4][4];
    #pragma unroll
    for (int i = 0; i < 4; i++)
        #pragma unroll
        for (int j = 0; j < 4; j++)
            #pragma unroll
            for (int q = 0; q < 4; q++) acc[i][j][q] = 0.f;

    // stage loader: 2 chunks of 16B per thread per tensor
    auto load_stage = [&](int c, int stg) {
        const int k0 = c * BK;
        const uint32_t sbase = sb + stg * STG_B;
        #pragma unroll
        for (int i = 0; i < 2; i++) {
            int f = i * 256 + tid;
            int r = f >> 2, q = f & 3;
            uint32_t so = (uint32_t)(r * ROW_B + q * 16);
            size_t ga = (size_t)(row0 + r) * ldaA + k0 + q * 8;
            size_t gb = (size_t)(n0 + r)   * ldaB + k0 + q * 8;
            cp_async16(sbase + OFF_AH + so, Ahg + ga);
            cp_async16(sbase + OFF_AL + so, Alg + ga);
            cp_async16(sbase + OFF_BH + so, Bhg + gb);
            cp_async16(sbase + OFF_BL + so, Blg + gb);
        }
        cp_commit();
    };

    load_stage(0, 0);

    const int lane16 = lane & 15;
    // ldmatrix address components (within a stage buffer)
    const uint32_t a_row_off = (uint32_t)((warp_m + (lane & 15)) * ROW_B + (lane >> 4) * 16);
    const uint32_t b_row_off = (uint32_t)((warp_n + (lane16 & 7)) * ROW_B + ((lane16 >> 3) & 1) * 16);

    for (int c = 0; c < chunks; c++) {
        const int cur = c & 1;
        if (c + 1 < chunks) { load_stage(c + 1, cur ^ 1); cp_wait<1>(); }
        else                { cp_wait<0>(); }
        __syncthreads();

        const uint32_t sbase = sb + cur * STG_B;
        #pragma unroll
        for (int s16 = 0; s16 < 2; s16++) {
            const uint32_t koff = (uint32_t)(s16 * 32);   // 16 elems * 2B
            uint32_t ah[4][4], al[4][4], bf[4][2];
            #pragma unroll
            for (int mt = 0; mt < 4; mt++) {
                ldm_x4(ah[mt][0], ah[mt][1], ah[mt][2], ah[mt][3],
                       sbase + OFF_AH + a_row_off + (uint32_t)(mt * 16 * ROW_B) + koff);
                ldm_x4(al[mt][0], al[mt][1], al[mt][2], al[mt][3],
                       sbase + OFF_AL + a_row_off + (uint32_t)(mt * 16 * ROW_B) + koff);
            }
            // Bh: AhBh + AlBh
            #pragma unroll
            for (int nt = 0; nt < 4; nt++)
                ldm_x2(bf[nt][0], bf[nt][1],
                       sbase + OFF_BH + b_row_off + (uint32_t)(nt * 8 * ROW_B) + koff);
            #pragma unroll
            for (int mt = 0; mt < 4; mt++)
                #pragma unroll
                for (int nt = 0; nt < 4; nt++) {
                    mma16816(acc[mt][nt], ah[mt], bf[nt]);
                    mma16816(acc[mt][nt], al[mt], bf[nt]);
                }
            // Bl: AhBl
            #pragma unroll
            for (int nt = 0; nt < 4; nt++)
                ldm_x2(bf[nt][0], bf[nt][1],
                       sbase + OFF_BL + b_row_off + (uint32_t)(nt * 8 * ROW_B) + koff);
            #pragma unroll
            for (int mt = 0; mt < 4; mt++)
                #pragma unroll
                for (int nt = 0; nt < 4; nt++)
                    mma16816(acc[mt][nt], ah[mt], bf[nt]);
        }
        __syncthreads();
    }

    // ---------------- epilogue ----------------
    const int rbase = row0 + warp_m + (lane >> 2);
    const int cbase = n0 + warp_n + (lane & 3) * 2;
    #pragma unroll
    for (int mt = 0; mt < 4; mt++) {
        #pragma unroll
        for (int half = 0; half < 2; half++) {
            const int row = rbase + mt * 16 + half * 8;
            const size_t rb = (size_t)row * HIDDEN;
            #pragma unroll
            for (int nt = 0; nt < 4; nt++) {
                const int col = cbase + nt * 8;
                float vx = acc[mt][nt][half * 2 + 0];
                float vy = acc[mt][nt][half * 2 + 1];
                if (MODE == 0 || MODE == 1 || MODE == 3) {
                    float2 b = *(const float2*)&bias[col];
                    vx += b.x; vy += b.y;
                }
                if (MODE == 1 || MODE == 3) {
                    float2 rr = *(const float2*)&res[rb + col];
                    vx += rr.x; vy += rr.y;
                }
                if (MODE == 0) {
                    *(float2*)&out0[rb + col] = make_float2(vx, vy);
                    *(float2*)&out1[rb + col] = make_float2(fmaxf(vx, 0.f), fmaxf(vy, 0.f));
                } else if (MODE == 1) {
                    *(float2*)&out1[rb + col] = make_float2(fmaxf(vx, 0.f), fmaxf(vy, 0.f));
                } else if (MODE == 2) {
                    *(float2*)&out0[rb + col] = make_float2(vx, vy);
                } else {
                    *(float2*)&out0[rb + col] = make_float2(fmaxf(vx, 0.f), fmaxf(vy, 0.f));
                }
            }
        }
    }
}

// ---------------- segment mean -----------------------------------------------
__global__ void zero_count_kernel() {
    int i = blockIdx.x * blockDim.x + threadIdx.x;
    if (i < N_MOLS) g_count[i] = 0;
}
__global__ void seg_prep_kernel(const int* __restrict__ seg) {
    int i = blockIdx.x * blockDim.x + threadIdx.x;
    int s = seg[i];
    atomicAdd(&g_count[s], 1);
    if (i == 0 || seg[i - 1] != s) g_start[s] = i;
}
__global__ void seg_mean_kernel(float* __restrict__ out) {
    int m = blockIdx.x;
    int c = threadIdx.x;
    int cnt = g_count[m];
    float v = 0.f;
    if (cnt > 0) {
        int st = g_start[m];
        float s = 0.f;
        for (int r = 0; r < cnt; r++)
            s += g_hid[(size_t)(st + r) * HIDDEN + c];
        v = s / (float)cnt;
    }
    out[(size_t)m * HIDDEN + c] = v;
}

// ---------------- launch ------------------------------------------------------
extern "C" void kernel_launch(void* const* d_in, const int* in_sizes, int n_in,
                              void* d_out, int out_size) {
    const float* atom_features = (const float*)d_in[0];
    const float* f_bonds       = (const float*)d_in[1];
    const int*   a2a           = (const int*)d_in[2];
    const int*   a2b           = (const int*)d_in[3];
    const int*   seg           = (const int*)d_in[4];
    const float* Wi            = (const float*)d_in[5];
    const float* bi            = (const float*)d_in[6];
    const float* Wh            = (const float*)d_in[7];
    const float* bh            = (const float*)d_in[8];
    const float* Wo            = (const float*)d_in[9];
    const float* bo            = (const float*)d_in[10];
    float* out = (float*)d_out;

    float *inp, *msg, *hid;
    cudaGetSymbolAddress((void**)&inp, g_inp);
    cudaGetSymbolAddress((void**)&msg, g_msg);
    cudaGetSymbolAddress((void**)&hid, g_hid);
    __nv_bfloat16 *afH, *afL, *neiH, *neiL;
    __nv_bfloat16 *wiH, *wiL, *whH, *whL, *wo1H, *wo1L, *wo2H, *wo2L;
    cudaGetSymbolAddress((void**)&afH, g_AfH);
    cudaGetSymbolAddress((void**)&afL, g_AfL);
    cudaGetSymbolAddress((void**)&neiH, g_neiH);
    cudaGetSymbolAddress((void**)&neiL, g_neiL);
    cudaGetSymbolAddress((void**)&wiH, g_WiTH);
    cudaGetSymbolAddress((void**)&wiL, g_WiTL);
    cudaGetSymbolAddress((void**)&whH, g_WhTH);
    cudaGetSymbolAddress((void**)&whL, g_WhTL);
    cudaGetSymbolAddress((void**)&wo1H, g_Wo1TH);
    cudaGetSymbolAddress((void**)&wo1L, g_Wo1TL);
    cudaGetSymbolAddress((void**)&wo2H, g_Wo2TH);
    cudaGetSymbolAddress((void**)&wo2L, g_Wo2TL);

    cudaFuncSetAttribute(tc_gemm<0>, cudaFuncAttributeMaxDynamicSharedMemorySize, SMEM_TOTAL);
    cudaFuncSetAttribute(tc_gemm<1>, cudaFuncAttributeMaxDynamicSharedMemorySize, SMEM_TOTAL);
    cudaFuncSetAttribute(tc_gemm<2>, cudaFuncAttributeMaxDynamicSharedMemorySize, SMEM_TOTAL);
    cudaFuncSetAttribute(tc_gemm<3>, cudaFuncAttributeMaxDynamicSharedMemorySize, SMEM_TOTAL);

    dim3 grid(HIDDEN / 128, N_ATOMS / 128);   // (2, 512)

    // conversions
    conv_atoms_kernel<<<(N_ATOMS * LDA_AF + 255) / 256, 256>>>(atom_features);
    conv_weight_kernel<<<(HIDDEN * LDA_AF + 255) / 256, 256>>>(Wi, ATOM_FDIM, LDA_AF, wiH, wiL);
    conv_weight_kernel<<<(HIDDEN * LDA_NEI + 255) / 256, 256>>>(Wh, HIDDEN + BOND_FDIM, LDA_NEI, whH, whL);
    conv_weight_kernel<<<(HIDDEN * LDA_AF + 255) / 256, 256>>>(Wo, ATOM_FDIM, LDA_AF, wo1H, wo1L);
    conv_weight_kernel<<<(HIDDEN * HIDDEN + 255) / 256, 256>>>(Wo + (size_t)ATOM_FDIM * HIDDEN,
                                                               HIDDEN, HIDDEN, wo2H, wo2L);

    // GEMM1: inp = af @ Wi + bi ; msg = relu(inp).  K=192 -> 6 chunks
    tc_gemm<0><<<grid, 256, SMEM_TOTAL>>>(afH, afL, LDA_AF, wiH, wiL, LDA_AF,
                                          6, bi, nullptr, inp, msg);

    // bond gather (loop-invariant) -> nei cols 256..319
    gather_b_kernel<<<N_ATOMS / 4, 256>>>(a2b, f_bonds);

    // 2 message-passing iterations: K=320 -> 10 chunks
    for (int it = 0; it < 2; it++) {
        gather_a_kernel<<<N_ATOMS / 4, 256>>>(a2a);
        tc_gemm<1><<<grid, 256, SMEM_TOTAL>>>(neiH, neiL, LDA_NEI, whH, whL, LDA_NEI,
                                              10, bh, inp, nullptr, msg);
    }

    // final a_message gather
    gather_a_kernel<<<N_ATOMS / 4, 256>>>(a2a);

    // hid = relu(af @ Wo1 + a_msg @ Wo2 + bo)
    tc_gemm<2><<<grid, 256, SMEM_TOTAL>>>(afH, afL, LDA_AF, wo1H, wo1L, LDA_AF,
                                          6, nullptr, nullptr, hid, nullptr);
    tc_gemm<3><<<grid, 256, SMEM_TOTAL>>>(neiH, neiL, LDA_NEI, wo2H, wo2L, HIDDEN,
                                          8, bo, hid, hid, nullptr);

    // segment mean
    zero_count_kernel<<<(N_MOLS + 255) / 256, 256>>>();
    seg_prep_kernel<<<N_ATOMS / 256, 256>>>(seg);
    seg_mean_kernel<<<N_MOLS, 256>>>(out);
}

// round 5
// speedup vs baseline: 2.0593x; 1.0022x over previous
#include <cuda_runtime.h>
#include <cuda_bf16.h>
#include <cstdint>

#define N_ATOMS   65536
#define ATOM_FDIM 133
#define BOND_TOTAL 147
#define BOND_FDIM 14
#define HIDDEN    256
#define MAX_NB    6
#define N_MOLS    2048

#define LDA_AF   160   // 133 -> 160 (5 chunks of 32)
#define LDA_H    256   // 8 chunks of 32

// ---------------- scratch (device globals) ----------------------------------
__device__ float g_res[(size_t)N_ATOMS * HIDDEN];   // residual (inp + bond + bh), later gather(Z)+bo
__device__ float g_Y[(size_t)N_ATOMS * HIDDEN];     // GEMM raw outputs (Y / Z)
__device__ float g_hid[(size_t)N_ATOMS * HIDDEN];   // final atom hiddens
__device__ __nv_bfloat16 g_AfH[(size_t)N_ATOMS * LDA_AF];
__device__ __nv_bfloat16 g_AfL[(size_t)N_ATOMS * LDA_AF];
__device__ __nv_bfloat16 g_msgH[(size_t)N_ATOMS * LDA_H];
__device__ __nv_bfloat16 g_msgL[(size_t)N_ATOMS * LDA_H];
// transposed split weights: [256 n][ldaK]
__device__ __nv_bfloat16 g_WiTH[(size_t)HIDDEN * LDA_AF];
__device__ __nv_bfloat16 g_WiTL[(size_t)HIDDEN * LDA_AF];
__device__ __nv_bfloat16 g_Wh1TH[(size_t)HIDDEN * LDA_H];
__device__ __nv_bfloat16 g_Wh1TL[(size_t)HIDDEN * LDA_H];
__device__ __nv_bfloat16 g_Wo1TH[(size_t)HIDDEN * LDA_AF];
__device__ __nv_bfloat16 g_Wo1TL[(size_t)HIDDEN * LDA_AF];
__device__ __nv_bfloat16 g_Wo2TH[(size_t)HIDDEN * LDA_H];
__device__ __nv_bfloat16 g_Wo2TL[(size_t)HIDDEN * LDA_H];
__device__ int g_start[N_MOLS];
__device__ int g_count[N_MOLS];

__device__ __forceinline__ void split_bf16(float v, __nv_bfloat16& h, __nv_bfloat16& l) {
    h = __float2bfloat16(v);
    l = __float2bfloat16(v - __bfloat162float(h));
}
__device__ __forceinline__ uint32_t smem_u32(const void* p) {
    uint32_t a;
    asm("{ .reg .u64 t; cvta.to.shared.u64 t, %1; cvt.u32.u64 %0, t; }" : "=r"(a) : "l"(p));
    return a;
}
__device__ __forceinline__ void cp_async16(uint32_t s, const void* g) {
    asm volatile("cp.async.cg.shared.global [%0], [%1], 16;" :: "r"(s), "l"(g));
}
__device__ __forceinline__ void cp_commit() {
    asm volatile("cp.async.commit_group;" ::: "memory");
}
template <int N>
__device__ __forceinline__ void cp_wait() {
    asm volatile("cp.async.wait_group %0;" :: "n"(N) : "memory");
}
__device__ __forceinline__ void ldm_x4(uint32_t& r0, uint32_t& r1, uint32_t& r2,
                                       uint32_t& r3, uint32_t addr) {
    asm volatile("ldmatrix.sync.aligned.m8n8.x4.shared.b16 {%0,%1,%2,%3}, [%4];"
                 : "=r"(r0), "=r"(r1), "=r"(r2), "=r"(r3) : "r"(addr));
}
__device__ __forceinline__ void ldm_x2(uint32_t& r0, uint32_t& r1, uint32_t addr) {
    asm volatile("ldmatrix.sync.aligned.m8n8.x2.shared.b16 {%0,%1}, [%2];"
                 : "=r"(r0), "=r"(r1) : "r"(addr));
}
__device__ __forceinline__ void mma16816(float* c, const uint32_t* a, const uint32_t* b) {
    asm volatile(
        "mma.sync.aligned.m16n8k16.row.col.f32.bf16.bf16.f32 "
        "{%0,%1,%2,%3}, {%4,%5,%6,%7}, {%8,%9}, {%0,%1,%2,%3};"
        : "+f"(c[0]), "+f"(c[1]), "+f"(c[2]), "+f"(c[3])
        : "r"(a[0]), "r"(a[1]), "r"(a[2]), "r"(a[3]), "r"(b[0]), "r"(b[1]));
}

// ---------------- prep kernels ----------------------------------------------
__global__ void conv_atoms_kernel(const float* __restrict__ af) {
    int idx = blockIdx.x * blockDim.x + threadIdx.x;
    if (idx >= N_ATOMS * LDA_AF) return;
    int r = idx / LDA_AF, c = idx - r * LDA_AF;
    float v = (c < ATOM_FDIM) ? af[(size_t)r * ATOM_FDIM + c] : 0.0f;
    __nv_bfloat16 h, l; split_bf16(v, h, l);
    g_AfH[idx] = h; g_AfL[idx] = l;
}

__global__ void conv_weight_kernel(const float* __restrict__ W, int Ksrc, int lda,
                                   __nv_bfloat16* __restrict__ dH,
                                   __nv_bfloat16* __restrict__ dL) {
    int idx = blockIdx.x * blockDim.x + threadIdx.x;
    if (idx >= HIDDEN * lda) return;
    int n = idx / lda, k = idx - n * lda;
    float v = (k < Ksrc) ? W[(size_t)k * HIDDEN + n] : 0.0f;
    __nv_bfloat16 h, l; split_bf16(v, h, l);
    dH[idx] = h; dL[idx] = l;
}

// ---------------- bond residual (loop-invariant): g_res += bh + nb @ Wh2 -----
__global__ void __launch_bounds__(256)
bond_res_kernel(const int* __restrict__ a2b, const float* __restrict__ f_bonds,
                const float* __restrict__ Wh, const float* __restrict__ bh) {
    __shared__ float W2[BOND_FDIM][HIDDEN];
    __shared__ float nb[4][BOND_FDIM];
    int tid = threadIdx.x;
    for (int i = tid; i < BOND_FDIM * HIDDEN; i += 256)
        W2[i >> 8][i & 255] = Wh[(size_t)(HIDDEN + (i >> 8)) * HIDDEN + (i & 255)];
    int g = tid >> 6, t = tid & 63;
    int atom = blockIdx.x * 4 + g;
    if (t < BOND_FDIM) {
        float s = 0.f;
        #pragma unroll
        for (int j = 0; j < MAX_NB; j++) {
            int b = a2b[atom * MAX_NB + j];
            s += f_bonds[(size_t)b * BOND_TOTAL + (BOND_TOTAL - BOND_FDIM) + t];
        }
        nb[g][t] = s;
    }
    __syncthreads();
    int col = t * 4;
    size_t base = (size_t)atom * HIDDEN + col;
    float4 r = *(float4*)&g_res[base];
    float4 b = *(const float4*)&bh[col];
    r.x += b.x; r.y += b.y; r.z += b.z; r.w += b.w;
    #pragma unroll
    for (int cc = 0; cc < BOND_FDIM; cc++) {
        float s = nb[g][cc];
        float4 w = *(float4*)&W2[cc][col];
        r.x += s * w.x; r.y += s * w.y; r.z += s * w.z; r.w += s * w.w;
    }
    *(float4*)&g_res[base] = r;
}

// ---------------- gathers ----------------------------------------------------
// msg = relu(g_res + sum_j Y[a2a[i,j]]) -> split bf16 msgH/msgL
__global__ void gather_relu_kernel(const int* __restrict__ a2a) {
    int atom = blockIdx.x * 4 + (threadIdx.x >> 6);
    int col  = (threadIdx.x & 63) * 4;
    int i0 = a2a[atom * MAX_NB + 0], i1 = a2a[atom * MAX_NB + 1];
    int i2 = a2a[atom * MAX_NB + 2], i3 = a2a[atom * MAX_NB + 3];
    int i4 = a2a[atom * MAX_NB + 4], i5 = a2a[atom * MAX_NB + 5];
    const float* Y = g_Y;
    float4 s = *(const float4*)&g_res[(size_t)atom * HIDDEN + col];
    float4 v;
    v = *(const float4*)&Y[(size_t)i0 * HIDDEN + col]; s.x+=v.x; s.y+=v.y; s.z+=v.z; s.w+=v.w;
    v = *(const float4*)&Y[(size_t)i1 * HIDDEN + col]; s.x+=v.x; s.y+=v.y; s.z+=v.z; s.w+=v.w;
    v = *(const float4*)&Y[(size_t)i2 * HIDDEN + col]; s.x+=v.x; s.y+=v.y; s.z+=v.z; s.w+=v.w;
    v = *(const float4*)&Y[(size_t)i3 * HIDDEN + col]; s.x+=v.x; s.y+=v.y; s.z+=v.z; s.w+=v.w;
    v = *(const float4*)&Y[(size_t)i4 * HIDDEN + col]; s.x+=v.x; s.y+=v.y; s.z+=v.z; s.w+=v.w;
    v = *(const float4*)&Y[(size_t)i5 * HIDDEN + col]; s.x+=v.x; s.y+=v.y; s.z+=v.z; s.w+=v.w;
    s.x = fmaxf(s.x, 0.f); s.y = fmaxf(s.y, 0.f);
    s.z = fmaxf(s.z, 0.f); s.w = fmaxf(s.w, 0.f);
    __nv_bfloat16 h0,h1,h2,h3,l0,l1,l2,l3;
    split_bf16(s.x, h0, l0); split_bf16(s.y, h1, l1);
    split_bf16(s.z, h2, l2); split_bf16(s.w, h3, l3);
    uint2 ph, pl;
    ph.x = ((uint32_t)__bfloat16_as_ushort(h1) << 16) | __bfloat16_as_ushort(h0);
    ph.y = ((uint32_t)__bfloat16_as_ushort(h3) << 16) | __bfloat16_as_ushort(h2);
    pl.x = ((uint32_t)__bfloat16_as_ushort(l1) << 16) | __bfloat16_as_ushort(l0);
    pl.y = ((uint32_t)__bfloat16_as_ushort(l3) << 16) | __bfloat16_as_ushort(l2);
    *(uint2*)&g_msgH[(size_t)atom * LDA_H + col] = ph;
    *(uint2*)&g_msgL[(size_t)atom * LDA_H + col] = pl;
}

// g_res = sum_j Z[a2a[i,j]] + bo   (fp32)
__global__ void gather_final_kernel(const int* __restrict__ a2a,
                                    const float* __restrict__ bo) {
    int atom = blockIdx.x * 4 + (threadIdx.x >> 6);
    int col  = (threadIdx.x & 63) * 4;
    int i0 = a2a[atom * MAX_NB + 0], i1 = a2a[atom * MAX_NB + 1];
    int i2 = a2a[atom * MAX_NB + 2], i3 = a2a[atom * MAX_NB + 3];
    int i4 = a2a[atom * MAX_NB + 4], i5 = a2a[atom * MAX_NB + 5];
    const float* Y = g_Y;
    float4 s = *(const float4*)&bo[col];
    float4 v;
    v = *(const float4*)&Y[(size_t)i0 * HIDDEN + col]; s.x+=v.x; s.y+=v.y; s.z+=v.z; s.w+=v.w;
    v = *(const float4*)&Y[(size_t)i1 * HIDDEN + col]; s.x+=v.x; s.y+=v.y; s.z+=v.z; s.w+=v.w;
    v = *(const float4*)&Y[(size_t)i2 * HIDDEN + col]; s.x+=v.x; s.y+=v.y; s.z+=v.z; s.w+=v.w;
    v = *(const float4*)&Y[(size_t)i3 * HIDDEN + col]; s.x+=v.x; s.y+=v.y; s.z+=v.z; s.w+=v.w;
    v = *(const float4*)&Y[(size_t)i4 * HIDDEN + col]; s.x+=v.x; s.y+=v.y; s.z+=v.z; s.w+=v.w;
    v = *(const float4*)&Y[(size_t)i5 * HIDDEN + col]; s.x+=v.x; s.y+=v.y; s.z+=v.z; s.w+=v.w;
    *(float4*)&g_res[(size_t)atom * HIDDEN + col] = s;
}

// ---------------- bf16x3 tensor-core GEMM ------------------------------------
// MODE 0: v=acc+bias; out0=v (fp32); relu(v) split -> outH/outL
// MODE 1: out0=acc (raw fp32)
// MODE 2: v=acc+res; out0=relu(v)
#define BK       32
#define ROW_B    80              // 32*2B + 16B pad
#define TILE_B   (128 * ROW_B)
#define OFF_AH   0
#define OFF_AL   TILE_B
#define OFF_BH   (2 * TILE_B)
#define OFF_BL   (3 * TILE_B)
#define STG_B    (4 * TILE_B)
#define SMEM_TOTAL (2 * STG_B)   // 81920

template <int MODE>
__global__ void __launch_bounds__(256, 2)
tc_gemm(const __nv_bfloat16* __restrict__ Ahg, const __nv_bfloat16* __restrict__ Alg, int ldaA,
        const __nv_bfloat16* __restrict__ Bhg, const __nv_bfloat16* __restrict__ Blg,
        int chunks,
        const float* __restrict__ bias, const float* __restrict__ res,
        float* __restrict__ out0,
        __nv_bfloat16* __restrict__ outH, __nv_bfloat16* __restrict__ outL)
{
    extern __shared__ char smem[];
    uint32_t sb = smem_u32(smem);
    const int tid  = threadIdx.x;
    const int wid  = tid >> 5;
    const int lane = tid & 31;
    const int row0 = blockIdx.y * 128;
    const int n0   = blockIdx.x * 128;
    const int warp_m = (wid >> 2) * 64;
    const int warp_n = (wid & 3) * 32;
    const int ldaB = chunks * BK;

    float acc[4][4][4];
    #pragma unroll
    for (int i = 0; i < 4; i++)
        #pragma unroll
        for (int j = 0; j < 4; j++)
            #pragma unroll
            for (int q = 0; q < 4; q++) acc[i][j][q] = 0.f;

    auto load_stage = [&](int c, int stg) {
        const int k0 = c * BK;
        const uint32_t sbase = sb + stg * STG_B;
        #pragma unroll
        for (int i = 0; i < 2; i++) {
            int f = i * 256 + tid;
            int r = f >> 2, q = f & 3;
            uint32_t so = (uint32_t)(r * ROW_B + q * 16);
            size_t ga = (size_t)(row0 + r) * ldaA + k0 + q * 8;
            size_t gb = (size_t)(n0 + r) * ldaB + k0 + q * 8;
            cp_async16(sbase + OFF_AH + so, Ahg + ga);
            cp_async16(sbase + OFF_AL + so, Alg + ga);
            cp_async16(sbase + OFF_BH + so, Bhg + gb);
            cp_async16(sbase + OFF_BL + so, Blg + gb);
        }
        cp_commit();
    };

    load_stage(0, 0);

    const int lane16 = lane & 15;
    const uint32_t a_row_off = (uint32_t)((warp_m + (lane & 15)) * ROW_B + (lane >> 4) * 16);
    const uint32_t b_row_off = (uint32_t)((warp_n + (lane16 & 7)) * ROW_B + ((lane16 >> 3) & 1) * 16);

    for (int c = 0; c < chunks; c++) {
        const int cur = c & 1;
        if (c + 1 < chunks) { load_stage(c + 1, cur ^ 1); cp_wait<1>(); }
        else                { cp_wait<0>(); }
        __syncthreads();

        const uint32_t sbase = sb + cur * STG_B;
        #pragma unroll
        for (int s16 = 0; s16 < 2; s16++) {
            const uint32_t koff = (uint32_t)(s16 * 32);
            uint32_t bh[4][2], bl[4][2];
            #pragma unroll
            for (int nt = 0; nt < 4; nt++) {
                ldm_x2(bh[nt][0], bh[nt][1],
                       sbase + OFF_BH + b_row_off + (uint32_t)(nt * 8 * ROW_B) + koff);
                ldm_x2(bl[nt][0], bl[nt][1],
                       sbase + OFF_BL + b_row_off + (uint32_t)(nt * 8 * ROW_B) + koff);
            }
            #pragma unroll
            for (int mt = 0; mt < 4; mt++) {
                uint32_t a[4];
                ldm_x4(a[0], a[1], a[2], a[3],
                       sbase + OFF_AH + a_row_off + (uint32_t)(mt * 16 * ROW_B) + koff);
                #pragma unroll
                for (int nt = 0; nt < 4; nt++) mma16816(acc[mt][nt], a, bh[nt]);
                #pragma unroll
                for (int nt = 0; nt < 4; nt++) mma16816(acc[mt][nt], a, bl[nt]);
                ldm_x4(a[0], a[1], a[2], a[3],
                       sbase + OFF_AL + a_row_off + (uint32_t)(mt * 16 * ROW_B) + koff);
                #pragma unroll
                for (int nt = 0; nt < 4; nt++) mma16816(acc[mt][nt], a, bh[nt]);
            }
        }
        __syncthreads();
    }

    // epilogue
    const int rbase = row0 + warp_m + (lane >> 2);
    const int cbase = n0 + warp_n + (lane & 3) * 2;
    #pragma unroll
    for (int mt = 0; mt < 4; mt++) {
        #pragma unroll
        for (int half = 0; half < 2; half++) {
            const int row = rbase + mt * 16 + half * 8;
            const size_t rb = (size_t)row * HIDDEN;
            #pragma unroll
            for (int nt = 0; nt < 4; nt++) {
                const int col = cbase + nt * 8;
                float vx = acc[mt][nt][half * 2 + 0];
                float vy = acc[mt][nt][half * 2 + 1];
                if (MODE == 0) {
                    float2 b = *(const float2*)&bias[col];
                    vx += b.x; vy += b.y;
                    *(float2*)&out0[rb + col] = make_float2(vx, vy);
                    float rx = fmaxf(vx, 0.f), ry = fmaxf(vy, 0.f);
                    __nv_bfloat16 hx, lx, hy, ly;
                    split_bf16(rx, hx, lx); split_bf16(ry, hy, ly);
                    *(uint32_t*)&outH[rb + col] =
                        ((uint32_t)__bfloat16_as_ushort(hy) << 16) | __bfloat16_as_ushort(hx);
                    *(uint32_t*)&outL[rb + col] =
                        ((uint32_t)__bfloat16_as_ushort(ly) << 16) | __bfloat16_as_ushort(lx);
                } else if (MODE == 1) {
                    *(float2*)&out0[rb + col] = make_float2(vx, vy);
                } else {
                    float2 rr = *(const float2*)&res[rb + col];
                    vx += rr.x; vy += rr.y;
                    *(float2*)&out0[rb + col] = make_float2(fmaxf(vx, 0.f), fmaxf(vy, 0.f));
                }
            }
        }
    }
}

// ---------------- segment mean -----------------------------------------------
__global__ void zero_count_kernel() {
    int i = blockIdx.x * blockDim.x + threadIdx.x;
    if (i < N_MOLS) g_count[i] = 0;
}
__global__ void seg_prep_kernel(const int* __restrict__ seg) {
    int i = blockIdx.x * blockDim.x + threadIdx.x;
    int s = seg[i];
    atomicAdd(&g_count[s], 1);
    if (i == 0 || seg[i - 1] != s) g_start[s] = i;
}
__global__ void seg_mean_kernel(float* __restrict__ out) {
    int m = blockIdx.x;
    int c = threadIdx.x;
    int cnt = g_count[m];
    float v = 0.f;
    if (cnt > 0) {
        int st = g_start[m];
        float s = 0.f;
        for (int r = 0; r < cnt; r++)
            s += g_hid[(size_t)(st + r) * HIDDEN + c];
        v = s / (float)cnt;
    }
    out[(size_t)m * HIDDEN + c] = v;
}

// ---------------- launch ------------------------------------------------------
extern "C" void kernel_launch(void* const* d_in, const int* in_sizes, int n_in,
                              void* d_out, int out_size) {
    const float* atom_features = (const float*)d_in[0];
    const float* f_bonds       = (const float*)d_in[1];
    const int*   a2a           = (const int*)d_in[2];
    const int*   a2b           = (const int*)d_in[3];
    const int*   seg           = (const int*)d_in[4];
    const float* Wi            = (const float*)d_in[5];
    const float* bi            = (const float*)d_in[6];
    const float* Wh            = (const float*)d_in[7];
    const float* bh            = (const float*)d_in[8];
    const float* Wo            = (const float*)d_in[9];
    const float* bo            = (const float*)d_in[10];
    float* out = (float*)d_out;

    float *resp, *Yp, *hidp;
    cudaGetSymbolAddress((void**)&resp, g_res);
    cudaGetSymbolAddress((void**)&Yp, g_Y);
    cudaGetSymbolAddress((void**)&hidp, g_hid);
    __nv_bfloat16 *afH, *afL, *msgH, *msgL;
    __nv_bfloat16 *wiH, *wiL, *wh1H, *wh1L, *wo1H, *wo1L, *wo2H, *wo2L;
    cudaGetSymbolAddress((void**)&afH, g_AfH);
    cudaGetSymbolAddress((void**)&afL, g_AfL);
    cudaGetSymbolAddress((void**)&msgH, g_msgH);
    cudaGetSymbolAddress((void**)&msgL, g_msgL);
    cudaGetSymbolAddress((void**)&wiH, g_WiTH);
    cudaGetSymbolAddress((void**)&wiL, g_WiTL);
    cudaGetSymbolAddress((void**)&wh1H, g_Wh1TH);
    cudaGetSymbolAddress((void**)&wh1L, g_Wh1TL);
    cudaGetSymbolAddress((void**)&wo1H, g_Wo1TH);
    cudaGetSymbolAddress((void**)&wo1L, g_Wo1TL);
    cudaGetSymbolAddress((void**)&wo2H, g_Wo2TH);
    cudaGetSymbolAddress((void**)&wo2L, g_Wo2TL);

    cudaFuncSetAttribute(tc_gemm<0>, cudaFuncAttributeMaxDynamicSharedMemorySize, SMEM_TOTAL);
    cudaFuncSetAttribute(tc_gemm<1>, cudaFuncAttributeMaxDynamicSharedMemorySize, SMEM_TOTAL);
    cudaFuncSetAttribute(tc_gemm<2>, cudaFuncAttributeMaxDynamicSharedMemorySize, SMEM_TOTAL);

    dim3 grid(HIDDEN / 128, N_ATOMS / 128);   // (2, 512)

    // conversions
    conv_atoms_kernel<<<(N_ATOMS * LDA_AF + 255) / 256, 256>>>(atom_features);
    conv_weight_kernel<<<(HIDDEN * LDA_AF + 255) / 256, 256>>>(Wi, ATOM_FDIM, LDA_AF, wiH, wiL);
    conv_weight_kernel<<<(HIDDEN * LDA_H + 255) / 256, 256>>>(Wh, HIDDEN, LDA_H, wh1H, wh1L);
    conv_weight_kernel<<<(HIDDEN * LDA_AF + 255) / 256, 256>>>(Wo, ATOM_FDIM, LDA_AF, wo1H, wo1L);
    conv_weight_kernel<<<(HIDDEN * LDA_H + 255) / 256, 256>>>(Wo + (size_t)ATOM_FDIM * HIDDEN,
                                                              HIDDEN, LDA_H, wo2H, wo2L);

    // GEMM1: g_res = af@Wi + bi ; msgH/L = split(relu(...)).  K=160 -> 5 chunks
    tc_gemm<0><<<grid, 256, SMEM_TOTAL>>>(afH, afL, LDA_AF, wiH, wiL, 5,
                                          bi, nullptr, resp, msgH, msgL);

    // loop-invariant residual: g_res += bh + nei_b_sum @ Wh2
    bond_res_kernel<<<N_ATOMS / 4, 256>>>(a2b, f_bonds, Wh, bh);

    // 2 message-passing iterations: Y = msg@Wh1 (K=256, 8 chunks); msg = relu(res + gather(Y))
    for (int it = 0; it < 2; it++) {
        tc_gemm<1><<<grid, 256, SMEM_TOTAL>>>(msgH, msgL, LDA_H, wh1H, wh1L, 8,
                                              nullptr, nullptr, Yp, nullptr, nullptr);
        gather_relu_kernel<<<N_ATOMS / 4, 256>>>(a2a);
    }

    // Z = msg@Wo2 (K=256); g_res = gather(Z) + bo
    tc_gemm<1><<<grid, 256, SMEM_TOTAL>>>(msgH, msgL, LDA_H, wo2H, wo2L, 8,
                                          nullptr, nullptr, Yp, nullptr, nullptr);
    gather_final_kernel<<<N_ATOMS / 4, 256>>>(a2a, bo);

    // hid = relu(af@Wo1 + g_res).  K=160
    tc_gemm<2><<<grid, 256, SMEM_TOTAL>>>(afH, afL, LDA_AF, wo1H, wo1L, 5,
                                          nullptr, resp, hidp, nullptr, nullptr);

    // segment mean
    zero_count_kernel<<<(N_MOLS + 255) / 256, 256>>>();
    seg_prep_kernel<<<N_ATOMS / 256, 256>>>(seg);
    seg_mean_kernel<<<N_MOLS, 256>>>(out);
}

// round 6
// speedup vs baseline: 2.6093x; 1.2671x over previous
#include <cuda_runtime.h>
#include <cuda_fp16.h>
#include <cstdint>

#define N_ATOMS   65536
#define ATOM_FDIM 133
#define BOND_TOTAL 147
#define BOND_FDIM 14
#define HIDDEN    256
#define MAX_NB    6
#define N_MOLS    2048

#define LDA_AF   160   // 133 -> 160 (5 chunks of 32)
#define LDA_H    256   // 8 chunks
#define N_AF_OUT 512   // [Wi | Wo1] merged

// ---------------- scratch ----------------------------------------------------
__device__ float g_res[(size_t)N_ATOMS * HIDDEN];   // inp + bond + bh
__device__ float g_P[(size_t)N_ATOMS * HIDDEN];     // af @ Wo1 (raw)
__device__ float g_hid[(size_t)N_ATOMS * HIDDEN];   // final atom hiddens
__device__ __half g_Y[(size_t)N_ATOMS * HIDDEN];    // GEMM raw outputs (fp16)
__device__ __half g_AfH[(size_t)N_ATOMS * LDA_AF];
__device__ __half g_AfL[(size_t)N_ATOMS * LDA_AF];
__device__ __half g_msgH[(size_t)N_ATOMS * LDA_H];
__device__ __half g_msgL[(size_t)N_ATOMS * LDA_H];
__device__ __half g_Waf[(size_t)N_AF_OUT * LDA_AF]; // [Wi|Wo1]^T fp16
__device__ __half g_Wh1T[(size_t)HIDDEN * LDA_H];
__device__ __half g_Wo2T[(size_t)HIDDEN * LDA_H];
__device__ int g_start[N_MOLS];
__device__ int g_count[N_MOLS];

__device__ __forceinline__ void split_f16(float v, __half& h, __half& l) {
    h = __float2half_rn(v);
    l = __float2half_rn(v - __half2float(h));
}
__device__ __forceinline__ uint32_t smem_u32(const void* p) {
    uint32_t a;
    asm("{ .reg .u64 t; cvta.to.shared.u64 t, %1; cvt.u32.u64 %0, t; }" : "=r"(a) : "l"(p));
    return a;
}
__device__ __forceinline__ void cp_async16(uint32_t s, const void* g) {
    asm volatile("cp.async.cg.shared.global [%0], [%1], 16;" :: "r"(s), "l"(g));
}
__device__ __forceinline__ void cp_commit() {
    asm volatile("cp.async.commit_group;" ::: "memory");
}
template <int N>
__device__ __forceinline__ void cp_wait() {
    asm volatile("cp.async.wait_group %0;" :: "n"(N) : "memory");
}
__device__ __forceinline__ void ldm_x4(uint32_t& r0, uint32_t& r1, uint32_t& r2,
                                       uint32_t& r3, uint32_t addr) {
    asm volatile("ldmatrix.sync.aligned.m8n8.x4.shared.b16 {%0,%1,%2,%3}, [%4];"
                 : "=r"(r0), "=r"(r1), "=r"(r2), "=r"(r3) : "r"(addr));
}
__device__ __forceinline__ void ldm_x2(uint32_t& r0, uint32_t& r1, uint32_t addr) {
    asm volatile("ldmatrix.sync.aligned.m8n8.x2.shared.b16 {%0,%1}, [%2];"
                 : "=r"(r0), "=r"(r1) : "r"(addr));
}
__device__ __forceinline__ void mma16816(float* c, const uint32_t* a, const uint32_t* b) {
    asm volatile(
        "mma.sync.aligned.m16n8k16.row.col.f32.f16.f16.f32 "
        "{%0,%1,%2,%3}, {%4,%5,%6,%7}, {%8,%9}, {%0,%1,%2,%3};"
        : "+f"(c[0]), "+f"(c[1]), "+f"(c[2]), "+f"(c[3])
        : "r"(a[0]), "r"(a[1]), "r"(a[2]), "r"(a[3]), "r"(b[0]), "r"(b[1]));
}

// ---------------- prep kernels -----------------------------------------------
__global__ void conv_atoms_kernel(const float* __restrict__ af) {
    int idx = blockIdx.x * blockDim.x + threadIdx.x;
    if (idx >= N_ATOMS * LDA_AF) return;
    int r = idx / LDA_AF, c = idx - r * LDA_AF;
    float v = (c < ATOM_FDIM) ? af[(size_t)r * ATOM_FDIM + c] : 0.0f;
    __half h, l; split_f16(v, h, l);
    g_AfH[idx] = h; g_AfL[idx] = l;
}

// [Wi | Wo1]^T rounded fp16: dst [512 n][160 k]
__global__ void conv_waf_kernel(const float* __restrict__ Wi,
                                const float* __restrict__ Wo) {
    int idx = blockIdx.x * blockDim.x + threadIdx.x;
    if (idx >= N_AF_OUT * LDA_AF) return;
    int n = idx / LDA_AF, k = idx - n * LDA_AF;
    float v = 0.f;
    if (k < ATOM_FDIM)
        v = (n < HIDDEN) ? Wi[(size_t)k * HIDDEN + n]
                         : Wo[(size_t)k * HIDDEN + (n - HIDDEN)];
    g_Waf[idx] = __float2half_rn(v);
}

// W^T rounded fp16: src rows [0..256) of W (stride HIDDEN) -> dst [256 n][256 k]
__global__ void conv_wT_kernel(const float* __restrict__ W, __half* __restrict__ dst) {
    int idx = blockIdx.x * blockDim.x + threadIdx.x;
    if (idx >= HIDDEN * LDA_H) return;
    int n = idx / LDA_H, k = idx - n * LDA_H;
    dst[idx] = __float2half_rn(W[(size_t)k * HIDDEN + n]);
}

// ---------------- bond residual: g_res += bh + nb @ Wh2 ----------------------
__global__ void __launch_bounds__(256)
bond_res_kernel(const int* __restrict__ a2b, const float* __restrict__ f_bonds,
                const float* __restrict__ Wh, const float* __restrict__ bh) {
    __shared__ float W2[BOND_FDIM][HIDDEN];
    __shared__ float nb[4][BOND_FDIM];
    int tid = threadIdx.x;
    for (int i = tid; i < BOND_FDIM * HIDDEN; i += 256)
        W2[i >> 8][i & 255] = Wh[(size_t)(HIDDEN + (i >> 8)) * HIDDEN + (i & 255)];
    int g = tid >> 6, t = tid & 63;
    int atom = blockIdx.x * 4 + g;
    if (t < BOND_FDIM) {
        float s = 0.f;
        #pragma unroll
        for (int j = 0; j < MAX_NB; j++) {
            int b = a2b[atom * MAX_NB + j];
            s += f_bonds[(size_t)b * BOND_TOTAL + (BOND_TOTAL - BOND_FDIM) + t];
        }
        nb[g][t] = s;
    }
    __syncthreads();
    int col = t * 4;
    size_t base = (size_t)atom * HIDDEN + col;
    float4 r = *(float4*)&g_res[base];
    float4 b = *(const float4*)&bh[col];
    r.x += b.x; r.y += b.y; r.z += b.z; r.w += b.w;
    #pragma unroll
    for (int cc = 0; cc < BOND_FDIM; cc++) {
        float s = nb[g][cc];
        float4 w = *(float4*)&W2[cc][col];
        r.x += s * w.x; r.y += s * w.y; r.z += s * w.z; r.w += s * w.w;
    }
    *(float4*)&g_res[base] = r;
}

// ---------------- gathers ----------------------------------------------------
__device__ __forceinline__ void add_y4(float4& s, const __half* Y, size_t base) {
    uint2 u = *(const uint2*)(Y + base);
    __half2 p0 = *(__half2*)&u.x;
    __half2 p1 = *(__half2*)&u.y;
    float2 f0 = __half22float2(p0), f1 = __half22float2(p1);
    s.x += f0.x; s.y += f0.y; s.z += f1.x; s.w += f1.y;
}

// msg = relu(g_res + sum_j Y[a2a[i,j]]) -> split fp16 msgH/msgL
__global__ void gather_relu_kernel(const int* __restrict__ a2a) {
    int atom = blockIdx.x * 4 + (threadIdx.x >> 6);
    int col  = (threadIdx.x & 63) * 4;
    int i0 = a2a[atom * MAX_NB + 0], i1 = a2a[atom * MAX_NB + 1];
    int i2 = a2a[atom * MAX_NB + 2], i3 = a2a[atom * MAX_NB + 3];
    int i4 = a2a[atom * MAX_NB + 4], i5 = a2a[atom * MAX_NB + 5];
    const __half* Y = g_Y;
    float4 s = *(const float4*)&g_res[(size_t)atom * HIDDEN + col];
    add_y4(s, Y, (size_t)i0 * HIDDEN + col);
    add_y4(s, Y, (size_t)i1 * HIDDEN + col);
    add_y4(s, Y, (size_t)i2 * HIDDEN + col);
    add_y4(s, Y, (size_t)i3 * HIDDEN + col);
    add_y4(s, Y, (size_t)i4 * HIDDEN + col);
    add_y4(s, Y, (size_t)i5 * HIDDEN + col);
    s.x = fmaxf(s.x, 0.f); s.y = fmaxf(s.y, 0.f);
    s.z = fmaxf(s.z, 0.f); s.w = fmaxf(s.w, 0.f);
    __half h0,h1,h2,h3,l0,l1,l2,l3;
    split_f16(s.x, h0, l0); split_f16(s.y, h1, l1);
    split_f16(s.z, h2, l2); split_f16(s.w, h3, l3);
    uint2 ph, pl;
    ph.x = ((uint32_t)__half_as_ushort(h1) << 16) | __half_as_ushort(h0);
    ph.y = ((uint32_t)__half_as_ushort(h3) << 16) | __half_as_ushort(h2);
    pl.x = ((uint32_t)__half_as_ushort(l1) << 16) | __half_as_ushort(l0);
    pl.y = ((uint32_t)__half_as_ushort(l3) << 16) | __half_as_ushort(l2);
    *(uint2*)&g_msgH[(size_t)atom * LDA_H + col] = ph;
    *(uint2*)&g_msgL[(size_t)atom * LDA_H + col] = pl;
}

// hid = relu(P + sum_j Z[a2a[i,j]] + bo)
__global__ void gather_final_kernel(const int* __restrict__ a2a,
                                    const float* __restrict__ bo) {
    int atom = blockIdx.x * 4 + (threadIdx.x >> 6);
    int col  = (threadIdx.x & 63) * 4;
    int i0 = a2a[atom * MAX_NB + 0], i1 = a2a[atom * MAX_NB + 1];
    int i2 = a2a[atom * MAX_NB + 2], i3 = a2a[atom * MAX_NB + 3];
    int i4 = a2a[atom * MAX_NB + 4], i5 = a2a[atom * MAX_NB + 5];
    const __half* Y = g_Y;
    size_t base = (size_t)atom * HIDDEN + col;
    float4 s = *(const float4*)&bo[col];
    float4 p = *(const float4*)&g_P[base];
    s.x += p.x; s.y += p.y; s.z += p.z; s.w += p.w;
    add_y4(s, Y, (size_t)i0 * HIDDEN + col);
    add_y4(s, Y, (size_t)i1 * HIDDEN + col);
    add_y4(s, Y, (size_t)i2 * HIDDEN + col);
    add_y4(s, Y, (size_t)i3 * HIDDEN + col);
    add_y4(s, Y, (size_t)i4 * HIDDEN + col);
    add_y4(s, Y, (size_t)i5 * HIDDEN + col);
    s.x = fmaxf(s.x, 0.f); s.y = fmaxf(s.y, 0.f);
    s.z = fmaxf(s.z, 0.f); s.w = fmaxf(s.w, 0.f);
    *(float4*)&g_hid[base] = s;
}

// ---------------- fp16 2-term tensor-core GEMM -------------------------------
// C = (Ah+Al) @ Bh.  MODE 0: dual-output af GEMM (N=512): n0<256 -> res+msg split,
// n0>=256 -> raw P.  MODE 1: Y = C (fp16 store).
#define BK       32
#define ROW_B    80               // 32*2B + 16B pad
#define TILE_B   (128 * ROW_B)    // 10240
#define STG_B    (3 * TILE_B)     // 30720 (AH, AL, BH)
#define SMEM_TOTAL (3 * STG_B)    // 92160, 3 stages

template <int MODE>
__global__ void __launch_bounds__(256, 2)
tc_gemm(const __half* __restrict__ Ahg, const __half* __restrict__ Alg, int ldaA,
        const __half* __restrict__ Bhg, int ldaB, int chunks,
        const float* __restrict__ bias,
        float* __restrict__ out_res, __half* __restrict__ outH, __half* __restrict__ outL,
        float* __restrict__ outP, __half* __restrict__ outY)
{
    extern __shared__ char smem[];
    uint32_t sb = smem_u32(smem);
    const int tid  = threadIdx.x;
    const int wid  = tid >> 5;
    const int lane = tid & 31;
    const int row0 = blockIdx.y * 128;
    const int n0   = blockIdx.x * 128;
    const int warp_m = (wid >> 2) * 64;
    const int warp_n = (wid & 3) * 32;

    float acc[4][4][4];
    #pragma unroll
    for (int i = 0; i < 4; i++)
        #pragma unroll
        for (int j = 0; j < 4; j++)
            #pragma unroll
            for (int q = 0; q < 4; q++) acc[i][j][q] = 0.f;

    auto load_stage = [&](int c, int stg) {
        const int k0 = c * BK;
        const uint32_t sbase = sb + stg * STG_B;
        #pragma unroll
        for (int i = 0; i < 2; i++) {
            int f = i * 256 + tid;
            int r = f >> 2, q = f & 3;
            uint32_t so = (uint32_t)(r * ROW_B + q * 16);
            size_t ga = (size_t)(row0 + r) * ldaA + k0 + q * 8;
            size_t gb = (size_t)(n0 + r) * ldaB + k0 + q * 8;
            cp_async16(sbase + 0 * TILE_B + so, Ahg + ga);
            cp_async16(sbase + 1 * TILE_B + so, Alg + ga);
            cp_async16(sbase + 2 * TILE_B + so, Bhg + gb);
        }
        cp_commit();
    };

    load_stage(0, 0);
    if (chunks > 1) load_stage(1, 1);

    const int lane16 = lane & 15;
    const uint32_t a_row_off = (uint32_t)((warp_m + (lane & 15)) * ROW_B + (lane >> 4) * 16);
    const uint32_t b_row_off = (uint32_t)((warp_n + (lane16 & 7)) * ROW_B + ((lane16 >> 3) & 1) * 16);

    int stg = 0;
    for (int c = 0; c < chunks; c++) {
        if (c == chunks - 1) cp_wait<0>(); else cp_wait<1>();
        __syncthreads();
        if (c + 2 < chunks) {
            int ns = stg + 2; if (ns >= 3) ns -= 3;
            load_stage(c + 2, ns);
        }
        const uint32_t sbase = sb + stg * STG_B;
        #pragma unroll
        for (int s16 = 0; s16 < 2; s16++) {
            const uint32_t koff = (uint32_t)(s16 * 32);
            uint32_t b[4][2];
            #pragma unroll
            for (int nt = 0; nt < 4; nt++)
                ldm_x2(b[nt][0], b[nt][1],
                       sbase + 2 * TILE_B + b_row_off + (uint32_t)(nt * 8 * ROW_B) + koff);
            #pragma unroll
            for (int mt = 0; mt < 4; mt++) {
                uint32_t a[4];
                ldm_x4(a[0], a[1], a[2], a[3],
                       sbase + 0 * TILE_B + a_row_off + (uint32_t)(mt * 16 * ROW_B) + koff);
                #pragma unroll
                for (int nt = 0; nt < 4; nt++) mma16816(acc[mt][nt], a, b[nt]);
                ldm_x4(a[0], a[1], a[2], a[3],
                       sbase + 1 * TILE_B + a_row_off + (uint32_t)(mt * 16 * ROW_B) + koff);
                #pragma unroll
                for (int nt = 0; nt < 4; nt++) mma16816(acc[mt][nt], a, b[nt]);
            }
        }
        if (++stg == 3) stg = 0;
    }

    // epilogue
    const int rbase = row0 + warp_m + (lane >> 2);
    const bool resPath = (MODE == 1) || (n0 < 256);
    const int cloc = ((MODE == 0 && n0 >= 256) ? n0 - 256 : n0) + warp_n + (lane & 3) * 2;
    #pragma unroll
    for (int mt = 0; mt < 4; mt++) {
        #pragma unroll
        for (int half_i = 0; half_i < 2; half_i++) {
            const int row = rbase + mt * 16 + half_i * 8;
            const size_t rb = (size_t)row * HIDDEN;
            #pragma unroll
            for (int nt = 0; nt < 4; nt++) {
                const int col = cloc + nt * 8;
                float vx = acc[mt][nt][half_i * 2 + 0];
                float vy = acc[mt][nt][half_i * 2 + 1];
                if (MODE == 1) {
                    __half2 h2 = __floats2half2_rn(vx, vy);
                    *(__half2*)&outY[rb + col] = h2;
                } else if (resPath) {
                    float2 b = *(const float2*)&bias[col];
                    vx += b.x; vy += b.y;
                    *(float2*)&out_res[rb + col] = make_float2(vx, vy);
                    float rx = fmaxf(vx, 0.f), ry = fmaxf(vy, 0.f);
                    __half hx, lx, hy, ly;
                    split_f16(rx, hx, lx); split_f16(ry, hy, ly);
                    *(uint32_t*)&outH[rb + col] =
                        ((uint32_t)__half_as_ushort(hy) << 16) | __half_as_ushort(hx);
                    *(uint32_t*)&outL[rb + col] =
                        ((uint32_t)__half_as_ushort(ly) << 16) | __half_as_ushort(lx);
                } else {
                    *(float2*)&outP[rb + col] = make_float2(vx, vy);
                }
            }
        }
    }
}

// ---------------- segment mean -----------------------------------------------
__global__ void zero_count_kernel() {
    int i = blockIdx.x * blockDim.x + threadIdx.x;
    if (i < N_MOLS) g_count[i] = 0;
}
__global__ void seg_prep_kernel(const int* __restrict__ seg) {
    int i = blockIdx.x * blockDim.x + threadIdx.x;
    int s = seg[i];
    atomicAdd(&g_count[s], 1);
    if (i == 0 || seg[i - 1] != s) g_start[s] = i;
}
__global__ void seg_mean_kernel(float* __restrict__ out) {
    int m = blockIdx.x;
    int c = threadIdx.x;
    int cnt = g_count[m];
    float v = 0.f;
    if (cnt > 0) {
        int st = g_start[m];
        float s = 0.f;
        for (int r = 0; r < cnt; r++)
            s += g_hid[(size_t)(st + r) * HIDDEN + c];
        v = s / (float)cnt;
    }
    out[(size_t)m * HIDDEN + c] = v;
}

// ---------------- launch ------------------------------------------------------
extern "C" void kernel_launch(void* const* d_in, const int* in_sizes, int n_in,
                              void* d_out, int out_size) {
    const float* atom_features = (const float*)d_in[0];
    const float* f_bonds       = (const float*)d_in[1];
    const int*   a2a           = (const int*)d_in[2];
    const int*   a2b           = (const int*)d_in[3];
    const int*   seg           = (const int*)d_in[4];
    const float* Wi            = (const float*)d_in[5];
    const float* bi            = (const float*)d_in[6];
    const float* Wh            = (const float*)d_in[7];
    const float* bh            = (const float*)d_in[8];
    const float* Wo            = (const float*)d_in[9];
    const float* bo            = (const float*)d_in[10];
    float* out = (float*)d_out;

    float *resp, *Pp;
    cudaGetSymbolAddress((void**)&resp, g_res);
    cudaGetSymbolAddress((void**)&Pp, g_P);
    __half *Yp, *afH, *afL, *msgH, *msgL, *waf, *wh1, *wo2;
    cudaGetSymbolAddress((void**)&Yp, g_Y);
    cudaGetSymbolAddress((void**)&afH, g_AfH);
    cudaGetSymbolAddress((void**)&afL, g_AfL);
    cudaGetSymbolAddress((void**)&msgH, g_msgH);
    cudaGetSymbolAddress((void**)&msgL, g_msgL);
    cudaGetSymbolAddress((void**)&waf, g_Waf);
    cudaGetSymbolAddress((void**)&wh1, g_Wh1T);
    cudaGetSymbolAddress((void**)&wo2, g_Wo2T);

    cudaFuncSetAttribute(tc_gemm<0>, cudaFuncAttributeMaxDynamicSharedMemorySize, SMEM_TOTAL);
    cudaFuncSetAttribute(tc_gemm<1>, cudaFuncAttributeMaxDynamicSharedMemorySize, SMEM_TOTAL);

    // conversions
    conv_atoms_kernel<<<(N_ATOMS * LDA_AF + 255) / 256, 256>>>(atom_features);
    conv_waf_kernel<<<(N_AF_OUT * LDA_AF + 255) / 256, 256>>>(Wi, Wo);
    conv_wT_kernel<<<(HIDDEN * LDA_H + 255) / 256, 256>>>(Wh, wh1);
    conv_wT_kernel<<<(HIDDEN * LDA_H + 255) / 256, 256>>>(Wo + (size_t)ATOM_FDIM * HIDDEN, wo2);

    // merged af GEMM: N=512, K=160 (5 chunks)
    //   n0<256: g_res = af@Wi + bi, msgH/L = split(relu(...))
    //   n0>=256: g_P = af@Wo1
    dim3 grid_af(N_AF_OUT / 128, N_ATOMS / 128);
    tc_gemm<0><<<grid_af, 256, SMEM_TOTAL>>>(afH, afL, LDA_AF, waf, LDA_AF, 5,
                                             bi, resp, msgH, msgL, Pp, nullptr);

    // loop-invariant residual
    bond_res_kernel<<<N_ATOMS / 4, 256>>>(a2b, f_bonds, Wh, bh);

    dim3 grid_h(HIDDEN / 128, N_ATOMS / 128);
    // 2 message-passing iterations
    for (int it = 0; it < 2; it++) {
        tc_gemm<1><<<grid_h, 256, SMEM_TOTAL>>>(msgH, msgL, LDA_H, wh1, LDA_H, 8,
                                                nullptr, nullptr, nullptr, nullptr, nullptr, Yp);
        gather_relu_kernel<<<N_ATOMS / 4, 256>>>(a2a);
    }

    // Z = msg @ Wo2 ; hid = relu(P + gather(Z) + bo)
    tc_gemm<1><<<grid_h, 256, SMEM_TOTAL>>>(msgH, msgL, LDA_H, wo2, LDA_H, 8,
                                            nullptr, nullptr, nullptr, nullptr, nullptr, Yp);
    gather_final_kernel<<<N_ATOMS / 4, 256>>>(a2a, bo);

    // segment mean
    zero_count_kernel<<<(N_MOLS + 255) / 256, 256>>>();
    seg_prep_kernel<<<N_ATOMS / 256, 256>>>(seg);
    seg_mean_kernel<<<N_MOLS, 256>>>(out);
}